// round 8
// baseline (speedup 1.0000x reference)
#include <cuda_runtime.h>
#include <cstdint>

// result = (1/B) * sum [ (81 + cw_h(r)*cw_w(c))*x^2 - 2*x*box9(x) ]
//        = 81*SA + 9*SB + SE - 2*Bh
// SA=Σx², SB=Σ cw_h x², SE=Σ cw_h dwc_w x², Bh=Σ x·box9(x).
// CPT=8: each thread owns 8 columns. Vertical 9-sum slides in registers
// (old/new row LDG). Horizontal 9-sum via shared halo exchange of the
// vertical sums (1 barrier per 2 rows, 4 rotating buffers). Row t is
// accumulated at its own step via an L1/L2-hit re-read LDG (no reg rings).

#define HH 512
#define WW 512
#define KRAD 4
#define TPB 64
#define STRIP 64
#define TILES (HH / STRIP)   // 8
#define NBLK 2048

__device__ double g_partials[NBLK];
__device__ unsigned int g_count = 0;

struct F8 { float4 a, b; };

__device__ __forceinline__ float cw_h(int r) {
    float w = 9.f;
    if (r < 4) w = (float)(5 + r);
    else if (r > HH - 5) w = (float)(HH + 4 - r);
    return w;
}

__device__ __forceinline__ F8 ldrow2(const float* __restrict__ Pc, int rr) {
    F8 v;
    v.a = make_float4(0.f, 0.f, 0.f, 0.f);
    v.b = make_float4(0.f, 0.f, 0.f, 0.f);
    if (rr >= 0 && rr < HH) {
        v.a = *(const float4*)(Pc + (size_t)rr * WW);
        v.b = *(const float4*)(Pc + (size_t)rr * WW + 4);
    }
    return v;
}

// publish current vsum (for row t) into buffer B, keep copies, slide to t+1
#define PUBSLIDE(B, t, VA, VB) do {                                            \
    *(float4*)&vsbuf[B][KRAD + c0]     = va;                                   \
    *(float4*)&vsbuf[B][KRAD + c0 + 4] = vb;                                   \
    VA = va; VB = vb;                                                          \
    F8 o = ldrow2(Pc, (t) - 4);                                                \
    F8 n = ldrow2(Pc, (t) + 5);                                                \
    va.x += n.a.x - o.a.x; va.y += n.a.y - o.a.y;                              \
    va.z += n.a.z - o.a.z; va.w += n.a.w - o.a.w;                              \
    vb.x += n.b.x - o.b.x; vb.y += n.b.y - o.b.y;                              \
    vb.z += n.b.z - o.b.z; vb.w += n.b.w - o.b.w;                              \
} while (0)

// after barrier: halos from buffer B, center from VA/VB copies; accumulate row t
#define ACCROW(B, t, VA, VB) do {                                              \
    float4 L = *(const float4*)&vsbuf[B][c0];                                  \
    float4 R = *(const float4*)&vsbuf[B][KRAD + c0 + 8];                       \
    float4 xa = *(const float4*)(Pc + (size_t)(t) * WW);                       \
    float4 xb = *(const float4*)(Pc + (size_t)(t) * WW + 4);                   \
    float h0 = ((L.x + L.y) + (L.z + L.w))                                     \
             + ((VA.x + VA.y) + (VA.z + VA.w)) + VB.x;                         \
    float h1 = h0 - L.x  + VB.y;                                               \
    float h2 = h1 - L.y  + VB.z;                                               \
    float h3 = h2 - L.z  + VB.w;                                               \
    float h4 = h3 - L.w  + R.x;                                                \
    float h5 = h4 - VA.x + R.y;                                                \
    float h6 = h5 - VA.y + R.z;                                                \
    float h7 = h6 - VA.z + R.w;                                                \
    Bh0 = fmaf(xa.x, h0, Bh0); Bh1 = fmaf(xa.y, h1, Bh1);                      \
    Bh0 = fmaf(xa.z, h2, Bh0); Bh1 = fmaf(xa.w, h3, Bh1);                      \
    Bh0 = fmaf(xb.x, h4, Bh0); Bh1 = fmaf(xb.y, h5, Bh1);                      \
    Bh0 = fmaf(xb.z, h6, Bh0); Bh1 = fmaf(xb.w, h7, Bh1);                      \
    float v0 = xa.x * xa.x, v1 = xa.y * xa.y;                                  \
    float v2 = xa.z * xa.z, v3 = xa.w * xa.w;                                  \
    float v4 = xb.x * xb.x, v5 = xb.y * xb.y;                                  \
    float v6 = xb.z * xb.z, v7 = xb.w * xb.w;                                  \
    float rs = ((v0 + v1) + (v2 + v3)) + ((v4 + v5) + (v6 + v7));              \
    float wr = cw_h(t);                                                        \
    SA += rs;                                                                  \
    SB = fmaf(wr, rs, SB);                                                     \
    if (has_dwc) {                                                             \
        float e = fmaf(dwa.x, v0, fmaf(dwa.y, v1,                              \
                  fmaf(dwa.z, v2, fmaf(dwa.w, v3,                              \
                  fmaf(dwb.x, v4, fmaf(dwb.y, v5,                              \
                  fmaf(dwb.z, v6, dwb.w * v7)))))));                           \
        SE = fmaf(wr, e, SE);                                                  \
    }                                                                          \
} while (0)

__global__ __launch_bounds__(TPB, 12) void scc_main_kernel(const float* __restrict__ img,
                                                           float* __restrict__ out,
                                                           double inv_b) {
    const int bid   = blockIdx.x;
    const int plane = bid >> 3;          // / TILES
    const int tile  = bid & (TILES - 1);
    const int r0    = tile * STRIP;
    const float* __restrict__ P = img + (size_t)plane * (HH * WW);

    const int tid = threadIdx.x;
    const int c0  = tid * 8;
    const float* __restrict__ Pc = P + c0;

    __shared__ float vsbuf[4][WW + 2 * KRAD];
    __shared__ double sred[2];
    __shared__ int slast;

    // zero horizontal halos once (4 buffers x 8 cells)
    if (tid < 32) {
        int b = tid >> 3;
        int i = tid & 7;
        int idx = (i < KRAD) ? i : (WW + i);   // 0..3, 516..519
        vsbuf[b][idx] = 0.0f;
    }

    // per-column cw_w deltas vs interior 9 (nonzero only threads 0 and 63)
    float4 dwa, dwb;
    {
        float d[8];
        #pragma unroll
        for (int i = 0; i < 8; i++) {
            int c = c0 + i;
            int l = (c < 4) ? (4 - c) : 0;
            int rr = (c > WW - 5) ? (c - (WW - 5)) : 0;
            d[i] = (float)(-l - rr);
        }
        dwa = make_float4(d[0], d[1], d[2], d[3]);
        dwb = make_float4(d[4], d[5], d[6], d[7]);
    }
    const bool has_dwc = (dwa.x != 0.f) || (dwb.w != 0.f);

    // prefill vertical sums for row r0 (rows r0-4 .. r0+4)
    float4 va = make_float4(0.f, 0.f, 0.f, 0.f);
    float4 vb = make_float4(0.f, 0.f, 0.f, 0.f);
    #pragma unroll
    for (int i = -KRAD; i <= KRAD; i++) {
        F8 v = ldrow2(Pc, r0 + i);
        va.x += v.a.x; va.y += v.a.y; va.z += v.a.z; va.w += v.a.w;
        vb.x += v.b.x; vb.y += v.b.y; vb.z += v.b.z; vb.w += v.b.w;
    }

    float SA = 0.f, SB = 0.f, SE = 0.f, Bh0 = 0.f, Bh1 = 0.f;
    float4 vsA0, vsB0, vsA1, vsB1;

    // 32 iterations x 2 rows, 1 barrier each; buffers rotate by iter parity
    #pragma unroll 2
    for (int it = 0; it < STRIP / 2; it++) {
        const int t  = r0 + 2 * it;
        const int pb = (it & 1) << 1;
        PUBSLIDE(pb,     t,     vsA0, vsB0);
        PUBSLIDE(pb + 1, t + 1, vsA1, vsB1);
        __syncthreads();
        ACCROW(pb,     t,     vsA0, vsB0);
        ACCROW(pb + 1, t + 1, vsA1, vsB1);
    }

    // combine in double:  81*SA + 9*SB + SE - 2*(Bh0+Bh1)
    double d = 81.0 * (double)SA + 9.0 * (double)SB
             + (double)SE - 2.0 * ((double)Bh0 + (double)Bh1);

    // block reduction (fixed order -> deterministic)
    const int w    = tid >> 5;
    const int lane = tid & 31;
    #pragma unroll
    for (int off = 16; off > 0; off >>= 1)
        d += __shfl_down_sync(0xffffffffu, d, off);
    if (lane == 0) sred[w] = d;
    __syncthreads();
    if (tid == 0) {
        g_partials[bid] = sred[0] + sred[1];
        __threadfence();
        unsigned int old = atomicAdd(&g_count, 1u);
        slast = (old == gridDim.x - 1) ? 1 : 0;
    }
    __syncthreads();

    // last block reduces all partials (fixed order -> deterministic)
    if (slast) {
        __threadfence();
        double t = 0.0;
        const int nb = gridDim.x;
        for (int i = tid; i < nb; i += TPB)
            t += g_partials[i];
        #pragma unroll
        for (int off = 16; off > 0; off >>= 1)
            t += __shfl_down_sync(0xffffffffu, t, off);
        if (lane == 0) sred[w] = t;
        __syncthreads();
        if (tid == 0) {
            out[0] = (float)((sred[0] + sred[1]) * inv_b);
            g_count = 0;   // reset for next graph replay
        }
    }
}

extern "C" void kernel_launch(void* const* d_in, const int* in_sizes, int n_in,
                              void* d_out, int out_size) {
    const float* img = (const float*)d_in[0];
    float* out = (float*)d_out;

    int nplanes = in_sizes[0] / (HH * WW);   // B*C = 256
    int batch   = nplanes / 32;              // C = 32 -> B = 8
    int nblocks = nplanes * TILES;           // 2048

    scc_main_kernel<<<nblocks, TPB>>>(img, out, 1.0 / (double)batch);
}